// round 15
// baseline (speedup 1.0000x reference)
#include <cuda_runtime.h>
#include <cuda_fp16.h>
#include <math.h>

#define HIDDEN 768
#define NH     12
#define HEAD   64
#define BATCH  2
#define SEQ    2048
#define M_TOT  (BATCH * SEQ)     // 4096
#define QKV_N  (3 * HIDDEN)      // 2304
#define CLOG2E 0.1803368801111204f   /* (1/8) * log2(e) */

// Scratch (allocation-free rule: __device__ globals)
__device__ __half g_xh[(size_t)M_TOT * HIDDEN];      // x fp16
__device__ __half g_wqkvt[(size_t)QKV_N * HIDDEN];   // W_qkv^T fp16 [2304][768]
__device__ __half g_woutt[(size_t)HIDDEN * HIDDEN];  // W_out^T fp16 [768][768]
__device__ __half g_qkvh[(size_t)M_TOT * QKV_N];     // qkv fp16 (Q pre-scaled)
__device__ __half g_atth[(size_t)M_TOT * HIDDEN];    // attention out fp16

// ---------------------------------------------------------------------------
// helpers
// ---------------------------------------------------------------------------
__device__ __forceinline__ void cp16(unsigned dst, const void* src) {
    asm volatile("cp.async.cg.shared.global [%0], [%1], 16;\n"
                 :: "r"(dst), "l"(src));
}
__device__ __forceinline__ void cp_commit() {
    asm volatile("cp.async.commit_group;\n" ::: "memory");
}
template <int N>
__device__ __forceinline__ void cp_wait() {
    asm volatile("cp.async.wait_group %0;\n" :: "n"(N) : "memory");
}

// D = A(16x16) * B(16x8) + D, fp16 in, f32 accum.
// c0=(g,2t) c1=(g,2t+1) c2=(g+8,2t) c3=(g+8,2t+1)   [g=lane>>2, t=lane&3]
__device__ __forceinline__ void mma16(float* c, const unsigned* a,
                                      unsigned b0, unsigned b1) {
    asm volatile(
        "mma.sync.aligned.m16n8k16.row.col.f32.f16.f16.f32 "
        "{%0,%1,%2,%3}, {%4,%5,%6,%7}, {%8,%9}, {%0,%1,%2,%3};"
        : "+f"(c[0]), "+f"(c[1]), "+f"(c[2]), "+f"(c[3])
        : "r"(a[0]), "r"(a[1]), "r"(a[2]), "r"(a[3]), "r"(b0), "r"(b1));
}
__device__ __forceinline__ void ldsm4(unsigned& r0, unsigned& r1, unsigned& r2,
                                      unsigned& r3, unsigned saddr) {
    asm volatile("ldmatrix.sync.aligned.m8n8.x4.shared.b16 {%0,%1,%2,%3}, [%4];"
                 : "=r"(r0), "=r"(r1), "=r"(r2), "=r"(r3) : "r"(saddr));
}
__device__ __forceinline__ void ldsm4t(unsigned& r0, unsigned& r1, unsigned& r2,
                                       unsigned& r3, unsigned saddr) {
    asm volatile("ldmatrix.sync.aligned.m8n8.x4.trans.shared.b16 {%0,%1,%2,%3}, [%4];"
                 : "=r"(r0), "=r"(r1), "=r"(r2), "=r"(r3) : "r"(saddr));
}
// pack two f32 -> f16x2 {hi, lo}
__device__ __forceinline__ unsigned pack_h2(float hi, float lo) {
    unsigned r;
    asm("cvt.rn.f16x2.f32 %0, %1, %2;" : "=r"(r) : "f"(hi), "f"(lo));
    return r;
}
// 2^x elementwise on fp16x2
__device__ __forceinline__ unsigned ex2_h2(unsigned x) {
    unsigned r;
    asm("ex2.approx.f16x2 %0, %1;" : "=r"(r) : "r"(x));
    return r;
}

// ---------------------------------------------------------------------------
// merged prepass: one launch does x->fp16 + both weight transposes.
// blocks [0,3072): f2h of x (786432 float4s)
// blocks [3072,4800): transpose W_qkv (72 x 24 tiles of 32x32)
// blocks [4800,5376): transpose W_out  (24 x 24 tiles)
// ---------------------------------------------------------------------------
#define PRE_F2H   3072
#define PRE_TQ    1728
#define PRE_BLKS  (PRE_F2H + PRE_TQ + 576)

__global__ __launch_bounds__(256)
void prepass_all(const float* __restrict__ x,
                 const float* __restrict__ Wq,
                 const float* __restrict__ Wo,
                 __half* __restrict__ xh,
                 __half* __restrict__ wqt,
                 __half* __restrict__ wot)
{
    __shared__ float tile[32][33];
    const int bid = blockIdx.x;
    const int tid = threadIdx.x;

    if (bid < PRE_F2H) {
        int i = bid * 256 + tid;          // < 786432 exactly
        float4 v = ((const float4*)x)[i];
        __half2 h0 = __floats2half2_rn(v.x, v.y);
        __half2 h1 = __floats2half2_rn(v.z, v.w);
        uint2 u;
        u.x = *reinterpret_cast<unsigned*>(&h0);
        u.y = *reinterpret_cast<unsigned*>(&h1);
        ((uint2*)xh)[i] = u;
        return;
    }

    const float* W;
    __half* Wt;
    int N, bx, by;
    if (bid < PRE_F2H + PRE_TQ) {
        int tb = bid - PRE_F2H;
        W = Wq; Wt = wqt; N = QKV_N;
        bx = tb % (QKV_N / 32); by = tb / (QKV_N / 32);
    } else {
        int tb = bid - (PRE_F2H + PRE_TQ);
        W = Wo; Wt = wot; N = HIDDEN;
        bx = tb % (HIDDEN / 32); by = tb / (HIDDEN / 32);
    }
    const int K = HIDDEN;
    const int tx = tid & 31, ty = tid >> 5;   // 32 x 8
    const int n0 = bx * 32, k0 = by * 32;
#pragma unroll
    for (int i = 0; i < 4; i++)
        tile[ty + 8 * i][tx] = W[(size_t)(k0 + ty + 8 * i) * N + n0 + tx];
    __syncthreads();
#pragma unroll
    for (int i = 0; i < 4; i++)
        Wt[(size_t)(n0 + ty + 8 * i) * K + k0 + tx] =
            __float2half_rn(tile[tx][ty + 8 * i]);
}

// ---------------------------------------------------------------------------
// fp16 GEMM with f32 bias (R11 design, kept): BM=BN=128, BK=64, 256 threads,
// 3-stage cp.async, hoisted addressing, ONE barrier per k-tile.
// ---------------------------------------------------------------------------
#define G_PITCH 72
#define G_STG_B (128 * G_PITCH * 2)
#define GEMM_SMEM (3 * 2 * G_STG_B)

__global__ __launch_bounds__(256, 2)
void gemm_h(const __half* __restrict__ A, const __half* __restrict__ Bt,
            const float* __restrict__ bias, void* __restrict__ Cv,
            int M, int Nn, int K, int out_half, int scale_q)
{
    extern __shared__ __half hsm[];
    const int tid  = threadIdx.x;
    const int lane = tid & 31;
    const int g    = lane >> 2;
    const int t    = lane & 3;
    const int warp = tid >> 5;
    const int wm0  = (warp >> 1) * 32;
    const int wn0  = (warp & 1) * 64;
    const int m0   = blockIdx.y * 128;
    const int n0   = blockIdx.x * 128;

    const unsigned base = (unsigned)__cvta_generic_to_shared(hsm);
    const unsigned BOFF = 3 * G_STG_B;

    const int frow = lane & 15;
    const int fcol = (lane >> 4) << 3;

    const int r0c  = tid >> 3;
    const int segc = tid & 7;
    const __half* aPs[4];
    const __half* bPs[4];
#pragma unroll
    for (int i = 0; i < 4; i++) {
        aPs[i] = A  + (size_t)(m0 + r0c + 32 * i) * K + segc * 8;
        bPs[i] = Bt + (size_t)(n0 + r0c + 32 * i) * K + segc * 8;
    }
    const unsigned offBase  = (unsigned)(r0c * G_PITCH + segc * 8) * 2;
    const unsigned rowStrid = 32 * G_PITCH * 2;

    float acc[2][8][4];
#pragma unroll
    for (int i = 0; i < 2; i++)
#pragma unroll
        for (int j = 0; j < 8; j++)
#pragma unroll
            for (int r = 0; r < 4; r++) acc[i][j][r] = 0.f;

    const int nk = K >> 6;

    unsigned istoff = 0;
#define GISSUE_HOIST()                                                          \
    {                                                                           \
        const unsigned sb = base + istoff;                                      \
        _Pragma("unroll")                                                       \
        for (int i = 0; i < 4; i++) {                                           \
            unsigned off = offBase + rowStrid * i;                              \
            cp16(sb + off, aPs[i]);                                             \
            cp16(sb + BOFF + off, bPs[i]);                                      \
            aPs[i] += 64; bPs[i] += 64;                                         \
        }                                                                       \
        cp_commit();                                                            \
        istoff = (istoff == 2 * G_STG_B) ? 0u : istoff + G_STG_B;               \
    }

    GISSUE_HOIST() GISSUE_HOIST()

    const unsigned aF = base + (unsigned)((wm0 + frow) * G_PITCH + fcol) * 2;
    const unsigned bF = base + BOFF + (unsigned)((wn0 + frow) * G_PITCH + fcol) * 2;

    unsigned stoff = 0;
    for (int kt = 0; kt < nk; kt++) {
        if (kt + 1 < nk) cp_wait<1>(); else cp_wait<0>();
        __syncthreads();
        if (kt + 2 < nk) GISSUE_HOIST()

        const unsigned aS = aF + stoff;
        const unsigned bS = bF + stoff;
        stoff = (stoff == 2 * G_STG_B) ? 0u : stoff + G_STG_B;

#pragma unroll
        for (int ks = 0; ks < 4; ks++) {
            const unsigned ko = (unsigned)(ks * 32);
            unsigned a0[4], a1[4];
            ldsm4(a0[0], a0[1], a0[2], a0[3], aS + ko);
            ldsm4(a1[0], a1[1], a1[2], a1[3], aS + ko + 16 * G_PITCH * 2);
#pragma unroll
            for (int p = 0; p < 4; p++) {
                unsigned r0, r1, r2, r3;
                ldsm4(r0, r1, r2, r3, bS + ko + (unsigned)(p * 16 * G_PITCH * 2));
                mma16(acc[0][2 * p],     a0, r0, r2);
                mma16(acc[0][2 * p + 1], a0, r1, r3);
                mma16(acc[1][2 * p],     a1, r0, r2);
                mma16(acc[1][2 * p + 1], a1, r1, r3);
            }
        }
    }

    const float cs = (scale_q && n0 < HIDDEN) ? CLOG2E : 1.0f;
#pragma unroll
    for (int am = 0; am < 2; am++) {
        int row = m0 + wm0 + am * 16 + g;
#pragma unroll
        for (int an = 0; an < 8; an++) {
            int col = n0 + wn0 + an * 8 + 2 * t;
            float2 bv = *(const float2*)&bias[col];
            float v00 = (acc[am][an][0] + bv.x) * cs, v01 = (acc[am][an][1] + bv.y) * cs;
            float v10 = (acc[am][an][2] + bv.x) * cs, v11 = (acc[am][an][3] + bv.y) * cs;
            if (out_half) {
                __half* Ch = (__half*)Cv;
                *(__half2*)&Ch[(size_t)row * Nn + col]       = __floats2half2_rn(v00, v01);
                *(__half2*)&Ch[(size_t)(row + 8) * Nn + col] = __floats2half2_rn(v10, v11);
            } else {
                float* Cf = (float*)Cv;
                *(float2*)&Cf[(size_t)row * Nn + col]       = make_float2(v00, v01);
                *(float2*)&Cf[(size_t)(row + 8) * Nn + col] = make_float2(v10, v11);
            }
        }
    }
}

// ---------------------------------------------------------------------------
// Flash attention (causal), fp16 mma m16n8k16, fixed-reference softmax,
// register-resident P (R12 numerics). 128 thr = 4 warps x 32 q-rows.
// OCCUPANCY 3: Q a-fragments are re-loaded per-ks inside the S loop (8 LDSM
// per tile) instead of being cached across the kernel — frees 32 persistent
// registers so 3 CTAs fit per SM (12 warps vs 8).
// smem (halves): Q[128][72] | K[2][64][72] | V[2][64][72] = 55296 B
// ---------------------------------------------------------------------------
#define ATTN_SMEM ((128 * 72 + 2 * 64 * 72 + 2 * 64 * 72) * 2)
#define ONES_H2 0x3C003C00u          /* fp16x2 {1.0, 1.0} */

__global__ __launch_bounds__(128, 3)
void attn_h(const __half* __restrict__ qkv, __half* __restrict__ out)
{
    extern __shared__ __half hsm[];
    const unsigned KS_OFF = 128 * 72;
    const unsigned VS_OFF = KS_OFF + 2 * 64 * 72;

    const int tid  = threadIdx.x;
    const int lane = tid & 31;
    const int g    = lane >> 2;
    const int t    = lane & 3;
    const int warp = tid >> 5;       // 0..3
    const int wm0  = warp * 32;      // 32 q-rows per warp
    const int qt   = 15 - (int)blockIdx.x;   // heavy tiles first
    const int h    = blockIdx.y;
    const int b    = blockIdx.z;
    const int q0   = qt * 128;

    const size_t base = (size_t)b * SEQ * QKV_N;
    const int qoff = h * HEAD;
    const int koff = HIDDEN + h * HEAD;
    const int voff = 2 * HIDDEN + h * HEAD;

    const unsigned smBase = (unsigned)__cvta_generic_to_shared(hsm);
    const int frow = lane & 15;
    const int fcol = (lane >> 4) << 3;
    const unsigned qpB0 = smBase + (unsigned)((wm0 + frow) * 72 + fcol) * 2;
    const unsigned qpB1 = smBase + (unsigned)((wm0 + 16 + frow) * 72 + fcol) * 2;

#define ATTN_ISSUE(stage, n0k_)                                                   \
    {                                                                             \
        int jr = tid >> 3, seg = tid & 7;                                         \
        _Pragma("unroll")                                                         \
        for (int i = 0; i < 4; i++) {                                             \
            int j = jr + 16 * i;                                                  \
            const __half* kp = qkv + base + (size_t)((n0k_) + j) * QKV_N + koff + seg * 8;\
            const __half* vp = qkv + base + (size_t)((n0k_) + j) * QKV_N + voff + seg * 8;\
            unsigned kd = smBase + (KS_OFF + (unsigned)((stage) * 64 + j) * 72 + seg * 8) * 2;\
            unsigned vd = smBase + (VS_OFF + (unsigned)((stage) * 64 + j) * 72 + seg * 8) * 2;\
            cp16(kd, kp);                                                         \
            cp16(vd, vp);                                                         \
        }                                                                         \
        cp_commit();                                                              \
    }

    // Q tile -> smem via cp.async (one-time; stays valid all tiles)
    {
#pragma unroll
        for (int it = 0; it < 8; it++) {
            int f = tid + 128 * it;
            int row = f >> 3, seg = f & 7;
            const __half* qp = qkv + base + (size_t)(q0 + row) * QKV_N + qoff + seg * 8;
            unsigned qd = smBase + (unsigned)(row * 72 + seg * 8) * 2;
            cp16(qd, qp);
        }
        cp_commit();
    }
    ATTN_ISSUE(0, 0)

    cp_wait<0>();
    __syncthreads();

    float o[2][8][4];
    float o9[2][4];
#pragma unroll
    for (int mb = 0; mb < 2; mb++) {
#pragma unroll
        for (int an = 0; an < 8; an++)
#pragma unroll
            for (int r = 0; r < 4; r++) o[mb][an][r] = 0.f;
#pragma unroll
        for (int r = 0; r < 4; r++) o9[mb][r] = 0.f;
    }

    const int ktiles = 2 * qt + 2;
    for (int kt = 0; kt < ktiles; kt++) {
        const int n0k = kt * 64;
        const int st  = kt & 1;

        if (kt > 0) {
            cp_wait<0>();
            __syncthreads();
        }
        if (kt + 1 < ktiles) ATTN_ISSUE(st ^ 1, n0k + 64)

        if (n0k <= q0 + wm0 + 31) {   // warp-level causal skip
            const unsigned kB = smBase + (KS_OFF + (unsigned)(st * 64 + frow) * 72 + fcol) * 2;
            const unsigned vB = smBase + (VS_OFF + (unsigned)(st * 64 + frow) * 72 + fcol) * 2;

            // ---- S = Q K^T; Q frags re-loaded per ks (saves 32 regs) ----
            float s0[8][4], s1[8][4];
#pragma unroll
            for (int an = 0; an < 8; an++)
#pragma unroll
                for (int r = 0; r < 4; r++) { s0[an][r] = 0.f; s1[an][r] = 0.f; }

#pragma unroll
            for (int ks = 0; ks < 4; ks++) {
                const unsigned ko = (unsigned)(ks * 32);
                unsigned qa0[4], qa1[4];
                ldsm4(qa0[0], qa0[1], qa0[2], qa0[3], qpB0 + ko);
                ldsm4(qa1[0], qa1[1], qa1[2], qa1[3], qpB1 + ko);
#pragma unroll
                for (int p = 0; p < 4; p++) {
                    unsigned r0, r1, r2, r3;
                    ldsm4(r0, r1, r2, r3, kB + ko + (unsigned)(p * 16 * 72 * 2));
                    mma16(s0[2 * p],     qa0, r0, r2);
                    mma16(s0[2 * p + 1], qa0, r1, r3);
                    mma16(s1[2 * p],     qa1, r0, r2);
                    mma16(s1[2 * p + 1], qa1, r1, r3);
                }
            }

            // ---- causal mask (rows wm0+g, +8, +16, +24) ----
            const int r0w = q0 + wm0 + g;
            if (n0k + 63 > q0 + wm0) {
#pragma unroll
                for (int an = 0; an < 8; an++) {
                    int c0 = n0k + an * 8 + 2 * t;
                    if (c0 > r0w)          s0[an][0] = -30000.f;
                    if (c0 + 1 > r0w)      s0[an][1] = -30000.f;
                    if (c0 > r0w + 8)      s0[an][2] = -30000.f;
                    if (c0 + 1 > r0w + 8)  s0[an][3] = -30000.f;
                    if (c0 > r0w + 16)     s1[an][0] = -30000.f;
                    if (c0 + 1 > r0w + 16) s1[an][1] = -30000.f;
                    if (c0 > r0w + 24)     s1[an][2] = -30000.f;
                    if (c0 + 1 > r0w + 24) s1[an][3] = -30000.f;
                }
            }

            // ---- p = 2^s packed straight into PV A-fragments ----
            unsigned pa0[4][4], pa1[4][4];
#pragma unroll
            for (int ks = 0; ks < 4; ks++) {
                pa0[ks][0] = ex2_h2(pack_h2(s0[2 * ks][1],     s0[2 * ks][0]));
                pa0[ks][1] = ex2_h2(pack_h2(s0[2 * ks][3],     s0[2 * ks][2]));
                pa0[ks][2] = ex2_h2(pack_h2(s0[2 * ks + 1][1], s0[2 * ks + 1][0]));
                pa0[ks][3] = ex2_h2(pack_h2(s0[2 * ks + 1][3], s0[2 * ks + 1][2]));
                pa1[ks][0] = ex2_h2(pack_h2(s1[2 * ks][1],     s1[2 * ks][0]));
                pa1[ks][1] = ex2_h2(pack_h2(s1[2 * ks][3],     s1[2 * ks][2]));
                pa1[ks][2] = ex2_h2(pack_h2(s1[2 * ks + 1][1], s1[2 * ks + 1][0]));
                pa1[ks][3] = ex2_h2(pack_h2(s1[2 * ks + 1][3], s1[2 * ks + 1][2]));
            }

            // ---- O += P V ; l += P @ ones — V-frags loaded once ----
#pragma unroll
            for (int ks = 0; ks < 4; ks++) {
#pragma unroll
                for (int p = 0; p < 4; p++) {
                    unsigned r0, r1, r2, r3;
                    ldsm4t(r0, r1, r2, r3,
                           vB + (unsigned)(ks * 16 * 72 * 2) + (unsigned)(p * 32));
                    mma16(o[0][2 * p],     pa0[ks], r0, r1);
                    mma16(o[0][2 * p + 1], pa0[ks], r2, r3);
                    mma16(o[1][2 * p],     pa1[ks], r0, r1);
                    mma16(o[1][2 * p + 1], pa1[ks], r2, r3);
                }
                mma16(o9[0], pa0[ks], ONES_H2, ONES_H2);
                mma16(o9[1], pa1[ks], ONES_H2, ONES_H2);
            }
        }
    }

    // ---- normalize + write fp16 ----
#pragma unroll
    for (int mb = 0; mb < 2; mb++) {
        const float inv0 = 1.0f / o9[mb][0], inv1 = 1.0f / o9[mb][2];
        const int rw = q0 + wm0 + mb * 16 + g;
#pragma unroll
        for (int an = 0; an < 8; an++) {
            int col = h * HEAD + an * 8 + 2 * t;
            *(__half2*)&out[((size_t)b * SEQ + rw) * HIDDEN + col] =
                __floats2half2_rn(o[mb][an][0] * inv0, o[mb][an][1] * inv0);
            *(__half2*)&out[((size_t)b * SEQ + rw + 8) * HIDDEN + col] =
                __floats2half2_rn(o[mb][an][2] * inv1, o[mb][an][3] * inv1);
        }
    }
}

// ---------------------------------------------------------------------------
extern "C" void kernel_launch(void* const* d_in, const int* in_sizes, int n_in,
                              void* d_out, int out_size)
{
    const float* x     = (const float*)d_in[0];
    const float* W_qkv = (const float*)d_in[1];
    const float* b_qkv = (const float*)d_in[2];
    const float* W_out = (const float*)d_in[3];
    const float* b_out = (const float*)d_in[4];
    float* out = (float*)d_out;

    __half *xh, *wqkvt, *woutt, *qkvh, *atth;
    cudaGetSymbolAddress((void**)&xh, g_xh);
    cudaGetSymbolAddress((void**)&wqkvt, g_wqkvt);
    cudaGetSymbolAddress((void**)&woutt, g_woutt);
    cudaGetSymbolAddress((void**)&qkvh, g_qkvh);
    cudaGetSymbolAddress((void**)&atth, g_atth);

    cudaFuncSetAttribute(gemm_h,
                         cudaFuncAttributeMaxDynamicSharedMemorySize, GEMM_SMEM);
    cudaFuncSetAttribute(attn_h,
                         cudaFuncAttributeMaxDynamicSharedMemorySize, ATTN_SMEM);

    // 0) merged prepass: x -> fp16; weights -> transposed fp16 (one launch)
    prepass_all<<<PRE_BLKS, 256>>>(x, W_qkv, W_out, xh, wqkvt, woutt);

    // 1) qkv = x @ W_qkv + b_qkv   (fp16 out; Q columns pre-scaled by CLOG2E)
    gemm_h<<<dim3(QKV_N / 128, M_TOT / 128), 256, GEMM_SMEM>>>(
        xh, wqkvt, b_qkv, qkvh, M_TOT, QKV_N, HIDDEN, 1, 1);

    // 2) causal flash attention    (fp16 out)
    attn_h<<<dim3(SEQ / 128, NH, BATCH), 128, ATTN_SMEM>>>(qkvh, atth);

    // 3) out = att @ W_out + b_out (f32 out)
    gemm_h<<<dim3(HIDDEN / 128, M_TOT / 128), 256, GEMM_SMEM>>>(
        atth, woutt, b_out, out, M_TOT, HIDDEN, HIDDEN, 0, 0);
}

// round 16
// speedup vs baseline: 1.0770x; 1.0770x over previous
#include <cuda_runtime.h>
#include <cuda_fp16.h>
#include <math.h>

#define HIDDEN 768
#define NH     12
#define HEAD   64
#define BATCH  2
#define SEQ    2048
#define M_TOT  (BATCH * SEQ)     // 4096
#define QKV_N  (3 * HIDDEN)      // 2304
#define CLOG2E 0.1803368801111204f   /* (1/8) * log2(e) */

// Scratch (allocation-free rule: __device__ globals)
__device__ __half g_xh[(size_t)M_TOT * HIDDEN];      // x fp16
__device__ __half g_wqkvt[(size_t)QKV_N * HIDDEN];   // W_qkv^T fp16 [2304][768]
__device__ __half g_woutt[(size_t)HIDDEN * HIDDEN];  // W_out^T fp16 [768][768]
__device__ __half g_qkvh[(size_t)M_TOT * QKV_N];     // qkv fp16 (Q pre-scaled)
__device__ __half g_atth[(size_t)M_TOT * HIDDEN];    // attention out fp16

// ---------------------------------------------------------------------------
// helpers
// ---------------------------------------------------------------------------
__device__ __forceinline__ void cp16(unsigned dst, const void* src) {
    asm volatile("cp.async.cg.shared.global [%0], [%1], 16;\n"
                 :: "r"(dst), "l"(src));
}
__device__ __forceinline__ void cp_commit() {
    asm volatile("cp.async.commit_group;\n" ::: "memory");
}
template <int N>
__device__ __forceinline__ void cp_wait() {
    asm volatile("cp.async.wait_group %0;\n" :: "n"(N) : "memory");
}

// D = A(16x16) * B(16x8) + D, fp16 in, f32 accum.
// c0=(g,2t) c1=(g,2t+1) c2=(g+8,2t) c3=(g+8,2t+1)   [g=lane>>2, t=lane&3]
__device__ __forceinline__ void mma16(float* c, const unsigned* a,
                                      unsigned b0, unsigned b1) {
    asm volatile(
        "mma.sync.aligned.m16n8k16.row.col.f32.f16.f16.f32 "
        "{%0,%1,%2,%3}, {%4,%5,%6,%7}, {%8,%9}, {%0,%1,%2,%3};"
        : "+f"(c[0]), "+f"(c[1]), "+f"(c[2]), "+f"(c[3])
        : "r"(a[0]), "r"(a[1]), "r"(a[2]), "r"(a[3]), "r"(b0), "r"(b1));
}
__device__ __forceinline__ void ldsm4(unsigned& r0, unsigned& r1, unsigned& r2,
                                      unsigned& r3, unsigned saddr) {
    asm volatile("ldmatrix.sync.aligned.m8n8.x4.shared.b16 {%0,%1,%2,%3}, [%4];"
                 : "=r"(r0), "=r"(r1), "=r"(r2), "=r"(r3) : "r"(saddr));
}
__device__ __forceinline__ void ldsm4t(unsigned& r0, unsigned& r1, unsigned& r2,
                                       unsigned& r3, unsigned saddr) {
    asm volatile("ldmatrix.sync.aligned.m8n8.x4.trans.shared.b16 {%0,%1,%2,%3}, [%4];"
                 : "=r"(r0), "=r"(r1), "=r"(r2), "=r"(r3) : "r"(saddr));
}
// pack two f32 -> f16x2 {hi, lo}
__device__ __forceinline__ unsigned pack_h2(float hi, float lo) {
    unsigned r;
    asm("cvt.rn.f16x2.f32 %0, %1, %2;" : "=r"(r) : "f"(hi), "f"(lo));
    return r;
}
// 2^x elementwise on fp16x2
__device__ __forceinline__ unsigned ex2_h2(unsigned x) {
    unsigned r;
    asm("ex2.approx.f16x2 %0, %1;" : "=r"(r) : "r"(x));
    return r;
}

// ---------------------------------------------------------------------------
// merged prepass: one launch does x->fp16 + both weight transposes.
// blocks [0,3072): f2h of x (786432 float4s)
// blocks [3072,4800): transpose W_qkv (72 x 24 tiles of 32x32)
// blocks [4800,5376): transpose W_out  (24 x 24 tiles)
// ---------------------------------------------------------------------------
#define PRE_F2H   3072
#define PRE_TQ    1728
#define PRE_BLKS  (PRE_F2H + PRE_TQ + 576)

__global__ __launch_bounds__(256)
void prepass_all(const float* __restrict__ x,
                 const float* __restrict__ Wq,
                 const float* __restrict__ Wo,
                 __half* __restrict__ xh,
                 __half* __restrict__ wqt,
                 __half* __restrict__ wot)
{
    __shared__ float tile[32][33];
    const int bid = blockIdx.x;
    const int tid = threadIdx.x;

    if (bid < PRE_F2H) {
        int i = bid * 256 + tid;          // < 786432 exactly
        float4 v = ((const float4*)x)[i];
        __half2 h0 = __floats2half2_rn(v.x, v.y);
        __half2 h1 = __floats2half2_rn(v.z, v.w);
        uint2 u;
        u.x = *reinterpret_cast<unsigned*>(&h0);
        u.y = *reinterpret_cast<unsigned*>(&h1);
        ((uint2*)xh)[i] = u;
        return;
    }

    const float* W;
    __half* Wt;
    int N, bx, by;
    if (bid < PRE_F2H + PRE_TQ) {
        int tb = bid - PRE_F2H;
        W = Wq; Wt = wqt; N = QKV_N;
        bx = tb % (QKV_N / 32); by = tb / (QKV_N / 32);
    } else {
        int tb = bid - (PRE_F2H + PRE_TQ);
        W = Wo; Wt = wot; N = HIDDEN;
        bx = tb % (HIDDEN / 32); by = tb / (HIDDEN / 32);
    }
    const int K = HIDDEN;
    const int tx = tid & 31, ty = tid >> 5;   // 32 x 8
    const int n0 = bx * 32, k0 = by * 32;
#pragma unroll
    for (int i = 0; i < 4; i++)
        tile[ty + 8 * i][tx] = W[(size_t)(k0 + ty + 8 * i) * N + n0 + tx];
    __syncthreads();
#pragma unroll
    for (int i = 0; i < 4; i++)
        Wt[(size_t)(n0 + ty + 8 * i) * K + k0 + tx] =
            __float2half_rn(tile[tx][ty + 8 * i]);
}

// ---------------------------------------------------------------------------
// fp16 GEMM with f32 bias (R11 design, kept): BM=BN=128, BK=64, 256 threads,
// 3-stage cp.async, hoisted addressing, ONE barrier per k-tile.
// ---------------------------------------------------------------------------
#define G_PITCH 72
#define G_STG_B (128 * G_PITCH * 2)
#define GEMM_SMEM (3 * 2 * G_STG_B)

__global__ __launch_bounds__(256, 2)
void gemm_h(const __half* __restrict__ A, const __half* __restrict__ Bt,
            const float* __restrict__ bias, void* __restrict__ Cv,
            int M, int Nn, int K, int out_half, int scale_q)
{
    extern __shared__ __half hsm[];
    const int tid  = threadIdx.x;
    const int lane = tid & 31;
    const int g    = lane >> 2;
    const int t    = lane & 3;
    const int warp = tid >> 5;
    const int wm0  = (warp >> 1) * 32;
    const int wn0  = (warp & 1) * 64;
    const int m0   = blockIdx.y * 128;
    const int n0   = blockIdx.x * 128;

    const unsigned base = (unsigned)__cvta_generic_to_shared(hsm);
    const unsigned BOFF = 3 * G_STG_B;

    const int frow = lane & 15;
    const int fcol = (lane >> 4) << 3;

    const int r0c  = tid >> 3;
    const int segc = tid & 7;
    const __half* aPs[4];
    const __half* bPs[4];
#pragma unroll
    for (int i = 0; i < 4; i++) {
        aPs[i] = A  + (size_t)(m0 + r0c + 32 * i) * K + segc * 8;
        bPs[i] = Bt + (size_t)(n0 + r0c + 32 * i) * K + segc * 8;
    }
    const unsigned offBase  = (unsigned)(r0c * G_PITCH + segc * 8) * 2;
    const unsigned rowStrid = 32 * G_PITCH * 2;

    float acc[2][8][4];
#pragma unroll
    for (int i = 0; i < 2; i++)
#pragma unroll
        for (int j = 0; j < 8; j++)
#pragma unroll
            for (int r = 0; r < 4; r++) acc[i][j][r] = 0.f;

    const int nk = K >> 6;

    unsigned istoff = 0;
#define GISSUE_HOIST()                                                          \
    {                                                                           \
        const unsigned sb = base + istoff;                                      \
        _Pragma("unroll")                                                       \
        for (int i = 0; i < 4; i++) {                                           \
            unsigned off = offBase + rowStrid * i;                              \
            cp16(sb + off, aPs[i]);                                             \
            cp16(sb + BOFF + off, bPs[i]);                                      \
            aPs[i] += 64; bPs[i] += 64;                                         \
        }                                                                       \
        cp_commit();                                                            \
        istoff = (istoff == 2 * G_STG_B) ? 0u : istoff + G_STG_B;               \
    }

    GISSUE_HOIST() GISSUE_HOIST()

    const unsigned aF = base + (unsigned)((wm0 + frow) * G_PITCH + fcol) * 2;
    const unsigned bF = base + BOFF + (unsigned)((wn0 + frow) * G_PITCH + fcol) * 2;

    unsigned stoff = 0;
    for (int kt = 0; kt < nk; kt++) {
        if (kt + 1 < nk) cp_wait<1>(); else cp_wait<0>();
        __syncthreads();
        if (kt + 2 < nk) GISSUE_HOIST()

        const unsigned aS = aF + stoff;
        const unsigned bS = bF + stoff;
        stoff = (stoff == 2 * G_STG_B) ? 0u : stoff + G_STG_B;

#pragma unroll
        for (int ks = 0; ks < 4; ks++) {
            const unsigned ko = (unsigned)(ks * 32);
            unsigned a0[4], a1[4];
            ldsm4(a0[0], a0[1], a0[2], a0[3], aS + ko);
            ldsm4(a1[0], a1[1], a1[2], a1[3], aS + ko + 16 * G_PITCH * 2);
#pragma unroll
            for (int p = 0; p < 4; p++) {
                unsigned r0, r1, r2, r3;
                ldsm4(r0, r1, r2, r3, bS + ko + (unsigned)(p * 16 * G_PITCH * 2));
                mma16(acc[0][2 * p],     a0, r0, r2);
                mma16(acc[0][2 * p + 1], a0, r1, r3);
                mma16(acc[1][2 * p],     a1, r0, r2);
                mma16(acc[1][2 * p + 1], a1, r1, r3);
            }
        }
    }

    const float cs = (scale_q && n0 < HIDDEN) ? CLOG2E : 1.0f;
#pragma unroll
    for (int am = 0; am < 2; am++) {
        int row = m0 + wm0 + am * 16 + g;
#pragma unroll
        for (int an = 0; an < 8; an++) {
            int col = n0 + wn0 + an * 8 + 2 * t;
            float2 bv = *(const float2*)&bias[col];
            float v00 = (acc[am][an][0] + bv.x) * cs, v01 = (acc[am][an][1] + bv.y) * cs;
            float v10 = (acc[am][an][2] + bv.x) * cs, v11 = (acc[am][an][3] + bv.y) * cs;
            if (out_half) {
                __half* Ch = (__half*)Cv;
                *(__half2*)&Ch[(size_t)row * Nn + col]       = __floats2half2_rn(v00, v01);
                *(__half2*)&Ch[(size_t)(row + 8) * Nn + col] = __floats2half2_rn(v10, v11);
            } else {
                float* Cf = (float*)Cv;
                *(float2*)&Cf[(size_t)row * Nn + col]       = make_float2(v00, v01);
                *(float2*)&Cf[(size_t)(row + 8) * Nn + col] = make_float2(v10, v11);
            }
        }
    }
}

// ---------------------------------------------------------------------------
// Flash attention (causal), fp16 mma m16n8k16, fixed-reference softmax,
// register-resident P — EXACT R12 kernel (best known).
// 128 thr = 4 warps x 32 q-rows (2 m-blocks); K/V frags loaded once per warp;
// double-buffered cp.async; l via all-ones mma column.
// smem (halves): Q[128][72] | K[2][64][72] | V[2][64][72] = 55296 B
// ---------------------------------------------------------------------------
#define ATTN_SMEM ((128 * 72 + 2 * 64 * 72 + 2 * 64 * 72) * 2)
#define ONES_H2 0x3C003C00u          /* fp16x2 {1.0, 1.0} */

__global__ __launch_bounds__(128, 2)
void attn_h(const __half* __restrict__ qkv, __half* __restrict__ out)
{
    extern __shared__ __half hsm[];
    const unsigned KS_OFF = 128 * 72;
    const unsigned VS_OFF = KS_OFF + 2 * 64 * 72;

    const int tid  = threadIdx.x;
    const int lane = tid & 31;
    const int g    = lane >> 2;
    const int t    = lane & 3;
    const int warp = tid >> 5;       // 0..3
    const int wm0  = warp * 32;      // 32 q-rows per warp
    const int qt   = 15 - (int)blockIdx.x;   // heavy tiles first
    const int h    = blockIdx.y;
    const int b    = blockIdx.z;
    const int q0   = qt * 128;

    const size_t base = (size_t)b * SEQ * QKV_N;
    const int qoff = h * HEAD;
    const int koff = HIDDEN + h * HEAD;
    const int voff = 2 * HIDDEN + h * HEAD;

    const unsigned smBase = (unsigned)__cvta_generic_to_shared(hsm);
    const int frow = lane & 15;
    const int fcol = (lane >> 4) << 3;
    const unsigned qpB0 = smBase + (unsigned)((wm0 + frow) * 72 + fcol) * 2;
    const unsigned qpB1 = smBase + (unsigned)((wm0 + 16 + frow) * 72 + fcol) * 2;

#define ATTN_ISSUE(stage, n0k_)                                                   \
    {                                                                             \
        int jr = tid >> 3, seg = tid & 7;                                         \
        _Pragma("unroll")                                                         \
        for (int i = 0; i < 4; i++) {                                             \
            int j = jr + 16 * i;                                                  \
            const __half* kp = qkv + base + (size_t)((n0k_) + j) * QKV_N + koff + seg * 8;\
            const __half* vp = qkv + base + (size_t)((n0k_) + j) * QKV_N + voff + seg * 8;\
            unsigned kd = smBase + (KS_OFF + (unsigned)((stage) * 64 + j) * 72 + seg * 8) * 2;\
            unsigned vd = smBase + (VS_OFF + (unsigned)((stage) * 64 + j) * 72 + seg * 8) * 2;\
            cp16(kd, kp);                                                         \
            cp16(vd, vp);                                                         \
        }                                                                         \
        cp_commit();                                                              \
    }

    // Q tile -> smem via cp.async (one-time)
    {
#pragma unroll
        for (int it = 0; it < 8; it++) {
            int f = tid + 128 * it;
            int row = f >> 3, seg = f & 7;
            const __half* qp = qkv + base + (size_t)(q0 + row) * QKV_N + qoff + seg * 8;
            unsigned qd = smBase + (unsigned)(row * 72 + seg * 8) * 2;
            cp16(qd, qp);
        }
        cp_commit();
    }
    ATTN_ISSUE(0, 0)

    cp_wait<0>();
    __syncthreads();

    // Q a-fragments -> registers for both m-blocks (cached for all tiles)
    unsigned qa[2][4][4];
#pragma unroll
    for (int ks = 0; ks < 4; ks++) {
        ldsm4(qa[0][ks][0], qa[0][ks][1], qa[0][ks][2], qa[0][ks][3],
              qpB0 + (unsigned)(ks * 32));
        ldsm4(qa[1][ks][0], qa[1][ks][1], qa[1][ks][2], qa[1][ks][3],
              qpB1 + (unsigned)(ks * 32));
    }

    float o[2][8][4];
    float o9[2][4];
#pragma unroll
    for (int mb = 0; mb < 2; mb++) {
#pragma unroll
        for (int an = 0; an < 8; an++)
#pragma unroll
            for (int r = 0; r < 4; r++) o[mb][an][r] = 0.f;
#pragma unroll
        for (int r = 0; r < 4; r++) o9[mb][r] = 0.f;
    }

    const int ktiles = 2 * qt + 2;
    for (int kt = 0; kt < ktiles; kt++) {
        const int n0k = kt * 64;
        const int st  = kt & 1;

        if (kt > 0) {
            cp_wait<0>();
            __syncthreads();
        }
        if (kt + 1 < ktiles) ATTN_ISSUE(st ^ 1, n0k + 64)

        if (n0k <= q0 + wm0 + 31) {   // warp-level causal skip
            const unsigned kB = smBase + (KS_OFF + (unsigned)(st * 64 + frow) * 72 + fcol) * 2;
            const unsigned vB = smBase + (VS_OFF + (unsigned)(st * 64 + frow) * 72 + fcol) * 2;

            // ---- S = Q K^T for both m-blocks; K-frags loaded once ----
            float s0[8][4], s1[8][4];
#pragma unroll
            for (int an = 0; an < 8; an++)
#pragma unroll
                for (int r = 0; r < 4; r++) { s0[an][r] = 0.f; s1[an][r] = 0.f; }

#pragma unroll
            for (int ks = 0; ks < 4; ks++) {
                const unsigned ko = (unsigned)(ks * 32);
#pragma unroll
                for (int p = 0; p < 4; p++) {
                    unsigned r0, r1, r2, r3;
                    ldsm4(r0, r1, r2, r3, kB + ko + (unsigned)(p * 16 * 72 * 2));
                    mma16(s0[2 * p],     qa[0][ks], r0, r2);
                    mma16(s0[2 * p + 1], qa[0][ks], r1, r3);
                    mma16(s1[2 * p],     qa[1][ks], r0, r2);
                    mma16(s1[2 * p + 1], qa[1][ks], r1, r3);
                }
            }

            // ---- causal mask (rows wm0+g, +8, +16, +24) ----
            const int r0w = q0 + wm0 + g;
            if (n0k + 63 > q0 + wm0) {
#pragma unroll
                for (int an = 0; an < 8; an++) {
                    int c0 = n0k + an * 8 + 2 * t;
                    if (c0 > r0w)          s0[an][0] = -30000.f;
                    if (c0 + 1 > r0w)      s0[an][1] = -30000.f;
                    if (c0 > r0w + 8)      s0[an][2] = -30000.f;
                    if (c0 + 1 > r0w + 8)  s0[an][3] = -30000.f;
                    if (c0 > r0w + 16)     s1[an][0] = -30000.f;
                    if (c0 + 1 > r0w + 16) s1[an][1] = -30000.f;
                    if (c0 > r0w + 24)     s1[an][2] = -30000.f;
                    if (c0 + 1 > r0w + 24) s1[an][3] = -30000.f;
                }
            }

            // ---- p = 2^s packed straight into PV A-fragments ----
            unsigned pa0[4][4], pa1[4][4];
#pragma unroll
            for (int ks = 0; ks < 4; ks++) {
                pa0[ks][0] = ex2_h2(pack_h2(s0[2 * ks][1],     s0[2 * ks][0]));
                pa0[ks][1] = ex2_h2(pack_h2(s0[2 * ks][3],     s0[2 * ks][2]));
                pa0[ks][2] = ex2_h2(pack_h2(s0[2 * ks + 1][1], s0[2 * ks + 1][0]));
                pa0[ks][3] = ex2_h2(pack_h2(s0[2 * ks + 1][3], s0[2 * ks + 1][2]));
                pa1[ks][0] = ex2_h2(pack_h2(s1[2 * ks][1],     s1[2 * ks][0]));
                pa1[ks][1] = ex2_h2(pack_h2(s1[2 * ks][3],     s1[2 * ks][2]));
                pa1[ks][2] = ex2_h2(pack_h2(s1[2 * ks + 1][1], s1[2 * ks + 1][0]));
                pa1[ks][3] = ex2_h2(pack_h2(s1[2 * ks + 1][3], s1[2 * ks + 1][2]));
            }

            // ---- O += P V ; l += P @ ones — V-frags loaded once ----
#pragma unroll
            for (int ks = 0; ks < 4; ks++) {
#pragma unroll
                for (int p = 0; p < 4; p++) {
                    unsigned r0, r1, r2, r3;
                    ldsm4t(r0, r1, r2, r3,
                           vB + (unsigned)(ks * 16 * 72 * 2) + (unsigned)(p * 32));
                    mma16(o[0][2 * p],     pa0[ks], r0, r1);
                    mma16(o[0][2 * p + 1], pa0[ks], r2, r3);
                    mma16(o[1][2 * p],     pa1[ks], r0, r1);
                    mma16(o[1][2 * p + 1], pa1[ks], r2, r3);
                }
                mma16(o9[0], pa0[ks], ONES_H2, ONES_H2);
                mma16(o9[1], pa1[ks], ONES_H2, ONES_H2);
            }
        }
    }

    // ---- normalize + write fp16 ----
#pragma unroll
    for (int mb = 0; mb < 2; mb++) {
        const float inv0 = 1.0f / o9[mb][0], inv1 = 1.0f / o9[mb][2];
        const int rw = q0 + wm0 + mb * 16 + g;
#pragma unroll
        for (int an = 0; an < 8; an++) {
            int col = h * HEAD + an * 8 + 2 * t;
            *(__half2*)&out[((size_t)b * SEQ + rw) * HIDDEN + col] =
                __floats2half2_rn(o[mb][an][0] * inv0, o[mb][an][1] * inv0);
            *(__half2*)&out[((size_t)b * SEQ + rw + 8) * HIDDEN + col] =
                __floats2half2_rn(o[mb][an][2] * inv1, o[mb][an][3] * inv1);
        }
    }
}

// ---------------------------------------------------------------------------
extern "C" void kernel_launch(void* const* d_in, const int* in_sizes, int n_in,
                              void* d_out, int out_size)
{
    const float* x     = (const float*)d_in[0];
    const float* W_qkv = (const float*)d_in[1];
    const float* b_qkv = (const float*)d_in[2];
    const float* W_out = (const float*)d_in[3];
    const float* b_out = (const float*)d_in[4];
    float* out = (float*)d_out;

    __half *xh, *wqkvt, *woutt, *qkvh, *atth;
    cudaGetSymbolAddress((void**)&xh, g_xh);
    cudaGetSymbolAddress((void**)&wqkvt, g_wqkvt);
    cudaGetSymbolAddress((void**)&woutt, g_woutt);
    cudaGetSymbolAddress((void**)&qkvh, g_qkvh);
    cudaGetSymbolAddress((void**)&atth, g_atth);

    cudaFuncSetAttribute(gemm_h,
                         cudaFuncAttributeMaxDynamicSharedMemorySize, GEMM_SMEM);
    cudaFuncSetAttribute(attn_h,
                         cudaFuncAttributeMaxDynamicSharedMemorySize, ATTN_SMEM);

    // 0) merged prepass: x -> fp16; weights -> transposed fp16 (one launch)
    prepass_all<<<PRE_BLKS, 256>>>(x, W_qkv, W_out, xh, wqkvt, woutt);

    // 1) qkv = x @ W_qkv + b_qkv   (fp16 out; Q columns pre-scaled by CLOG2E)
    gemm_h<<<dim3(QKV_N / 128, M_TOT / 128), 256, GEMM_SMEM>>>(
        xh, wqkvt, b_qkv, qkvh, M_TOT, QKV_N, HIDDEN, 1, 1);

    // 2) causal flash attention    (fp16 out)
    attn_h<<<dim3(SEQ / 128, NH, BATCH), 128, ATTN_SMEM>>>(qkvh, atth);

    // 3) out = att @ W_out + b_out (f32 out)
    gemm_h<<<dim3(HIDDEN / 128, M_TOT / 128), 256, GEMM_SMEM>>>(
        atth, woutt, b_out, out, M_TOT, HIDDEN, HIDDEN, 0, 0);
}